// round 5
// baseline (speedup 1.0000x reference)
#include <cuda_runtime.h>
#include <math.h>

#define BB    64
#define DD    1024
#define LL    2048
#define DH    512
#define SPLIT 16
#define LC    (LL / SPLIT)   // 128 rows per CTA
#define NP2   (LC / 16)      // 8 pairs per warp (8 warps, 2 rows each)

// ---------------- device scratch (16B-aligned) ----------------
__device__ __align__(16) float g_target[BB * DD];
__device__ __align__(16) float g_acc5[BB * DD];
__device__ __align__(16) float g_wctx[BB * DD];
__device__ __align__(16) float g_pm[BB * 2 * SPLIT];
__device__ __align__(16) float g_ps[BB * 2 * SPLIT];
__device__ __align__(16) float g_pacc[BB * 2 * SPLIT * DH];
__device__ __align__(16) float g_ms[BB * 2 * 2];
__device__ unsigned g_tile_ctr[16];

// ---------------- launch idx 0: zero g_target ----------------
__global__ void prep_a() {
    for (int i = blockIdx.x * 256 + threadIdx.x; i < BB * DD; i += 64 * 256)
        g_target[i] = 0.f;
}
// ---------------- launch idx 2: zero g_acc5 + tile counters ----------------
__global__ void prep_b() {
    int i0 = blockIdx.x * 256 + threadIdx.x;
    for (int i = i0; i < BB * DD; i += 64 * 256) g_acc5[i] = 0.f;
    if (i0 < 16) g_tile_ctr[i0] = 0u;
}

// ---------------- split-K NT GEMM body (M=64, 64x64 tile, 256 thr, atomic) ----
__device__ __forceinline__ void gemm_body(const float* __restrict__ A, int lda,
                                          const float* __restrict__ B, int ldb,
                                          float* __restrict__ C, int kchunk,
                                          int n0, int k0) {
    __shared__ __align__(16) float As[16][68];
    __shared__ __align__(16) float Bs[16][68];
    int tid  = threadIdx.x;
    int tx   = tid & 15, ty = tid >> 4;
    int lrow = tid >> 2, lcol = (tid & 3) << 2;

    const float* Ap = A + (size_t)lrow * lda + lcol;
    const float* Bp = B + (size_t)(n0 + lrow) * ldb + lcol;

    float acc[4][4];
#pragma unroll
    for (int i = 0; i < 4; i++)
#pragma unroll
        for (int j = 0; j < 4; j++) acc[i][j] = 0.f;

    for (int kk = k0; kk < k0 + kchunk; kk += 16) {
        float4 a = *(const float4*)(Ap + kk);
        float4 b = *(const float4*)(Bp + kk);
        __syncthreads();
        As[lcol + 0][lrow] = a.x; As[lcol + 1][lrow] = a.y;
        As[lcol + 2][lrow] = a.z; As[lcol + 3][lrow] = a.w;
        Bs[lcol + 0][lrow] = b.x; Bs[lcol + 1][lrow] = b.y;
        Bs[lcol + 2][lrow] = b.z; Bs[lcol + 3][lrow] = b.w;
        __syncthreads();
#pragma unroll
        for (int k = 0; k < 16; k++) {
            float4 av = *(const float4*)&As[k][ty << 2];
            float4 bv = *(const float4*)&Bs[k][tx << 2];
            float aa[4] = {av.x, av.y, av.z, av.w};
            float bb[4] = {bv.x, bv.y, bv.z, bv.w};
#pragma unroll
            for (int i = 0; i < 4; i++)
#pragma unroll
                for (int j = 0; j < 4; j++)
                    acc[i][j] = fmaf(aa[i], bb[j], acc[i][j]);
        }
    }
    int row = ty << 2, col = n0 + (tx << 2);
#pragma unroll
    for (int i = 0; i < 4; i++)
#pragma unroll
        for (int j = 0; j < 4; j++)
            atomicAdd(&C[(size_t)(row + i) * DD + col + j], acc[i][j]);
}

// ---------------- launch idx 1: g_target += input @ W_in^T ----------------
__global__ __launch_bounds__(256) void gemm_in(const float* __restrict__ inp,
                                               const float* __restrict__ Win) {
    gemm_body(inp, DD, Win, DD, g_target, DD / 8,
              blockIdx.x * 64, blockIdx.y * (DD / 8));
}

// ---------------- launch idx 3: fused attention + hidden gemm ----------------
// grid (16, 72), 256 threads. y<64: attention CTA (b=y, sp=x).
// y>=64: g_acc5 += input @ W_out[:,1024:2048]^T  (tile=x, split=y-64).
__global__ __launch_bounds__(256) void attn_fused(const float* __restrict__ ctx,
                                                  float* __restrict__ attn0,
                                                  float* __restrict__ attn1,
                                                  const float* __restrict__ inp,
                                                  const float* __restrict__ Wout) {
    if (blockIdx.y >= 64) {
        gemm_body(inp, DD, Wout + DD, 2 * DD, g_acc5, DD / 8,
                  blockIdx.x * 64, (blockIdx.y - 64) * (DD / 8));
        return;
    }
    const int b = blockIdx.y, sp = blockIdx.x;
    const int tid = threadIdx.x, lane = tid & 31, w = tid >> 5;

    __shared__ __align__(16) float sq[2][4][32][4];   // 4 KB lane-ordered q
    __shared__ float sacc[2][DH];                     // 4 KB
    __shared__ float slog[2][LC];                     // 1 KB raw logits
    __shared__ float smx[2][8], ssm[2][8];

    // sq[k][j][l][t] = target[b, (l+32j)*8 + 2t + k]
    for (int f = tid; f < 256; f += 256) {
        int k = f >> 7, j = (f >> 5) & 3, l = f & 31;
        const float* g = g_target + (size_t)b * DD + (size_t)(l + 32 * j) * 8 + k;
        float4 v; v.x = g[0]; v.y = g[2]; v.z = g[4]; v.w = g[6];
        *(float4*)&sq[k][j][l][0] = v;
    }
    for (int i = tid; i < 2 * DH; i += 256) (&sacc[0][0])[i] = 0.f;
    __syncthreads();

    const float4* base = (const float4*)(ctx + ((size_t)b * LL + (size_t)sp * LC) * DH);

    float a0[16], a1[16];
#pragma unroll
    for (int i = 0; i < 16; i++) { a0[i] = 0.f; a1[i] = 0.f; }
    float m0 = -1e30f, m1 = -1e30f, s0 = 0.f, s1 = 0.f;

    // buf[stage][row-in-pair][j] ; warp w pair p covers rows 16p+2w, 16p+2w+1
    float4 buf[2][2][4];
    {
        const float4* rp = base + (size_t)(2 * w) * (DH / 4);
#pragma unroll
        for (int j = 0; j < 4; j++) {
            buf[0][0][j] = rp[lane + 32 * j];
            buf[0][1][j] = rp[128 + lane + 32 * j];
        }
    }

#pragma unroll 2
    for (int p = 0; p < NP2; p++) {
        const int st = p & 1;
        if (p + 1 < NP2) {
            const float4* rp = base + (size_t)(16 * (p + 1) + 2 * w) * (DH / 4);
#pragma unroll
            for (int j = 0; j < 4; j++) {
                buf[st ^ 1][0][j] = rp[lane + 32 * j];
                buf[st ^ 1][1][j] = rp[128 + lane + 32 * j];
            }
        }

        float dA0 = 0.f, dA1 = 0.f, dB0 = 0.f, dB1 = 0.f;
#pragma unroll
        for (int j = 0; j < 4; j++) {
            float4 q0v = *(const float4*)&sq[0][j][lane][0];
            float4 q1v = *(const float4*)&sq[1][j][lane][0];
            float4 va = buf[st][0][j], vb = buf[st][1][j];
            dA0 = fmaf(va.x, q0v.x, dA0); dA0 = fmaf(va.y, q0v.y, dA0);
            dA0 = fmaf(va.z, q0v.z, dA0); dA0 = fmaf(va.w, q0v.w, dA0);
            dA1 = fmaf(va.x, q1v.x, dA1); dA1 = fmaf(va.y, q1v.y, dA1);
            dA1 = fmaf(va.z, q1v.z, dA1); dA1 = fmaf(va.w, q1v.w, dA1);
            dB0 = fmaf(vb.x, q0v.x, dB0); dB0 = fmaf(vb.y, q0v.y, dB0);
            dB0 = fmaf(vb.z, q0v.z, dB0); dB0 = fmaf(vb.w, q0v.w, dB0);
            dB1 = fmaf(vb.x, q1v.x, dB1); dB1 = fmaf(vb.y, q1v.y, dB1);
            dB1 = fmaf(vb.z, q1v.z, dB1); dB1 = fmaf(vb.w, q1v.w, dB1);
        }
#pragma unroll
        for (int o = 16; o; o >>= 1) {
            dA0 += __shfl_xor_sync(0xffffffffu, dA0, o);
            dA1 += __shfl_xor_sync(0xffffffffu, dA1, o);
            dB0 += __shfl_xor_sync(0xffffffffu, dB0, o);
            dB1 += __shfl_xor_sync(0xffffffffu, dB1, o);
        }
        int r = 16 * p + 2 * w;
        if (lane == 0) {
            slog[0][r] = dA0; slog[0][r + 1] = dB0;
            slog[1][r] = dA1; slog[1][r + 1] = dB1;
        }
        // pairwise online softmax; r==1 exactly when max unchanged (exp(0)=1)
        float n0 = fmaxf(m0, fmaxf(dA0, dB0));
        float n1 = fmaxf(m1, fmaxf(dA1, dB1));
        float r0 = __expf(m0 - n0), r1 = __expf(m1 - n1);
        float eA0 = __expf(dA0 - n0), eB0 = __expf(dB0 - n0);
        float eA1 = __expf(dA1 - n1), eB1 = __expf(dB1 - n1);
        s0 = s0 * r0 + eA0 + eB0; m0 = n0;
        s1 = s1 * r1 + eA1 + eB1; m1 = n1;
        if (r0 != 1.f || r1 != 1.f) {
#pragma unroll
            for (int i = 0; i < 16; i++) { a0[i] *= r0; a1[i] *= r1; }
        }
#pragma unroll
        for (int j = 0; j < 4; j++) {
            float4 va = buf[st][0][j], vb = buf[st][1][j];
            a0[4 * j + 0] = fmaf(eB0, vb.x, fmaf(eA0, va.x, a0[4 * j + 0]));
            a0[4 * j + 1] = fmaf(eB0, vb.y, fmaf(eA0, va.y, a0[4 * j + 1]));
            a0[4 * j + 2] = fmaf(eB0, vb.z, fmaf(eA0, va.z, a0[4 * j + 2]));
            a0[4 * j + 3] = fmaf(eB0, vb.w, fmaf(eA0, va.w, a0[4 * j + 3]));
            a1[4 * j + 0] = fmaf(eB1, vb.x, fmaf(eA1, va.x, a1[4 * j + 0]));
            a1[4 * j + 1] = fmaf(eB1, vb.y, fmaf(eA1, va.y, a1[4 * j + 1]));
            a1[4 * j + 2] = fmaf(eB1, vb.z, fmaf(eA1, va.z, a1[4 * j + 2]));
            a1[4 * j + 3] = fmaf(eB1, vb.w, fmaf(eA1, va.w, a1[4 * j + 3]));
        }
    }

    // ---- combine 8 warps within the CTA ----
    if (lane == 0) {
        smx[0][w] = m0; smx[1][w] = m1;
        ssm[0][w] = s0; ssm[1][w] = s1;
    }
    __syncthreads();

    // bulk coalesced store of raw logits (normalized later in final_k)
    {
        float* a0p = attn0 + (size_t)b * LL + sp * LC;
        float* a1p = attn1 + (size_t)b * LL + sp * LC;
        for (int i = tid; i < LC; i += 256) { a0p[i] = slog[0][i]; a1p[i] = slog[1][i]; }
    }

    float M0 = -1e30f, M1 = -1e30f;
#pragma unroll
    for (int ww = 0; ww < 8; ww++) {
        M0 = fmaxf(M0, smx[0][ww]);
        M1 = fmaxf(M1, smx[1][ww]);
    }
    float f0 = __expf(m0 - M0);
    float f1 = __expf(m1 - M1);
#pragma unroll
    for (int j = 0; j < 4; j++)
#pragma unroll
        for (int t = 0; t < 4; t++) {
            int d = (lane + 32 * j) * 4 + t;
            atomicAdd(&sacc[0][d], a0[4 * j + t] * f0);
            atomicAdd(&sacc[1][d], a1[4 * j + t] * f1);
        }
    __syncthreads();

    int idx0 = (b * 2 + 0) * SPLIT + sp;
    int idx1 = (b * 2 + 1) * SPLIT + sp;
    if (tid == 0) {
        float S0 = 0.f, S1 = 0.f;
#pragma unroll
        for (int ww = 0; ww < 8; ww++) {
            S0 += ssm[0][ww] * __expf(smx[0][ww] - M0);
            S1 += ssm[1][ww] * __expf(smx[1][ww] - M1);
        }
        g_pm[idx0] = M0; g_ps[idx0] = S0;
        g_pm[idx1] = M1; g_ps[idx1] = S1;
    }
    for (int i = tid; i < DH; i += 256) {
        g_pacc[(size_t)idx0 * DH + i] = sacc[0][i];
        g_pacc[(size_t)idx1 * DH + i] = sacc[1][i];
    }
}

// ---------------- launch idx 4: combine SPLIT partials (parallel M/S) --------
__global__ __launch_bounds__(256) void combine2() {
    int bk = blockIdx.x;                 // 0..127 = b*2+k
    __shared__ float wgt[SPLIT];
    __shared__ float sInv;
    if (threadIdx.x < 16) {
        float mv = g_pm[bk * SPLIT + threadIdx.x];
        float M = mv;
#pragma unroll
        for (int o = 8; o; o >>= 1) M = fmaxf(M, __shfl_xor_sync(0x0000ffffu, M, o));
        float wv = __expf(mv - M);
        wgt[threadIdx.x] = wv;
        float sv = g_ps[bk * SPLIT + threadIdx.x] * wv;
#pragma unroll
        for (int o = 8; o; o >>= 1) sv += __shfl_xor_sync(0x0000ffffu, sv, o);
        if (threadIdx.x == 0) {
            float inv = 1.0f / sv;
            sInv = inv;
            g_ms[bk * 2] = M; g_ms[bk * 2 + 1] = inv;
        }
    }
    __syncthreads();
    float inv = sInv;
    int b = bk >> 1, k = bk & 1;
    const float* pa = g_pacc + (size_t)bk * SPLIT * DH;
    for (int d = threadIdx.x; d < DH; d += 256) {
        float acc = 0.f;
#pragma unroll
        for (int sp = 0; sp < SPLIT; sp++) acc += pa[(size_t)sp * DH + d] * wgt[sp];
        g_wctx[(size_t)b * DD + k * DH + d] = acc * inv;
    }
}

// ---------------- launch idx 5: output GEMM + tanh, co-scheduled attn norm ----
// x<128: gemm tile=x>>3, split=x&7 (g_acc5 += g_wctx @ W_out[:,0:1024]^T).
// x>=128: 64 CTAs normalize attn logits elementwise using g_ms.
__global__ __launch_bounds__(256) void final_k(const float* __restrict__ Wout,
                                               float* __restrict__ out) {
    if (blockIdx.x < 128) {
        int tile = blockIdx.x >> 3, split = blockIdx.x & 7;
        gemm_body(g_wctx, DD, Wout, 2 * DD, g_acc5, DD / 8,
                  tile * 64, split * (DD / 8));
        __threadfence();
        __shared__ unsigned s_old;
        __syncthreads();
        if (threadIdx.x == 0) s_old = atomicAdd(&g_tile_ctr[tile], 1u);
        __syncthreads();
        if (s_old == 7u) {
            __threadfence();
            int n0 = tile * 64;
            for (int i = threadIdx.x; i < 64 * 64; i += 256) {
                int r = i >> 6, c = i & 63;
                out[(size_t)r * DD + n0 + c] = tanhf(g_acc5[(size_t)r * DD + n0 + c]);
            }
        }
    } else {
        float* attn = out + BB * DD;     // [attn0 | attn1], each BB*LL
        int start = (blockIdx.x - 128) * 256 + threadIdx.x;
        for (int i = start; i < 2 * BB * LL; i += 64 * 256) {
            int k = i >> 17;             // / (BB*LL)
            int b = (i & (BB * LL - 1)) >> 11;  // / LL
            int bk = b * 2 + k;
            attn[i] = __expf(attn[i] - g_ms[bk * 2]) * g_ms[bk * 2 + 1];
        }
    }
}

// ---------------- launcher ----------------
extern "C" void kernel_launch(void* const* d_in, const int* in_sizes, int n_in,
                              void* d_out, int out_size) {
    const float* input   = (const float*)d_in[0]; // [64,1024]
    const float* context = (const float*)d_in[1]; // [64,2048,512]
    const float* W_in    = (const float*)d_in[2]; // [1024,1024]
    const float* W_out   = (const float*)d_in[3]; // [1024,2048]
    float* out = (float*)d_out;                   // [ctxOut | attn0 | attn1]

    prep_a<<<64, 256>>>();                                   // idx 0
    gemm_in<<<dim3(16, 8), 256>>>(input, W_in);              // idx 1
    prep_b<<<64, 256>>>();                                   // idx 2
    attn_fused<<<dim3(16, 72), 256>>>(context,               // idx 3 (profiled)
                                      out + BB * DD,
                                      out + BB * DD + BB * LL,
                                      input, W_out);
    combine2<<<128, 256>>>();                                // idx 4
    final_k<<<192, 256>>>(W_out, out);                       // idx 5
}

// round 6
// speedup vs baseline: 1.1749x; 1.1749x over previous
#include <cuda_runtime.h>
#include <cuda_pipeline.h>
#include <math.h>

#define BB    64
#define DD    1024
#define LL    2048
#define DH    512
#define SPLIT 16
#define LC    (LL / SPLIT)   // 128 rows per CTA
#define NPAIR (LC / 16)      // 8 pairs per warp (8 warps, 2 rows each)

// dynamic smem layout (floats): ring[8][3][2][512] | sq 1024 | sacc 1024 | slog 256 | smx 16 | ssm 16
#define RING_F (8 * 3 * 2 * 512)
#define SMEM_F (RING_F + 1024 + 1024 + 256 + 16 + 16)
#define SMEM_B (SMEM_F * 4)

// ---------------- device scratch (16B-aligned) ----------------
__device__ __align__(16) float g_target[BB * DD];
__device__ __align__(16) float g_acc5[BB * DD];
__device__ __align__(16) float g_wctx[BB * DD];
__device__ __align__(16) float g_pm[BB * 2 * SPLIT];
__device__ __align__(16) float g_ps[BB * 2 * SPLIT];
__device__ __align__(16) float g_pacc[BB * 2 * SPLIT * DH];
__device__ __align__(16) float g_ms[BB * 2 * 2];
__device__ unsigned g_tile_ctr[16];

// ---------------- idx 0: zero atomic accumulators ----------------
__global__ void prep_kernel() {
    int i = blockIdx.x * 256 + threadIdx.x;
    if (i < BB * DD) { g_target[i] = 0.f; g_acc5[i] = 0.f; }
}
// ---------------- idx 2: zero tile counters (tiny; keeps attn at idx 3) ------
__global__ void zero_ctr() {
    if (threadIdx.x < 16) g_tile_ctr[threadIdx.x] = 0u;
}

// ---------------- split-K NT GEMM body (M=64, 64x64 tile, atomic epilogue) ----
__device__ __forceinline__ void gemm_body(const float* __restrict__ A, int lda,
                                          const float* __restrict__ B, int ldb,
                                          float* __restrict__ C, int kchunk,
                                          int n0, int k0) {
    __shared__ __align__(16) float As[16][68];
    __shared__ __align__(16) float Bs[16][68];
    int tid  = threadIdx.x;
    int tx   = tid & 15, ty = tid >> 4;
    int lrow = tid >> 2, lcol = (tid & 3) << 2;

    const float* Ap = A + (size_t)lrow * lda + lcol;
    const float* Bp = B + (size_t)(n0 + lrow) * ldb + lcol;

    float acc[4][4];
#pragma unroll
    for (int i = 0; i < 4; i++)
#pragma unroll
        for (int j = 0; j < 4; j++) acc[i][j] = 0.f;

    for (int kk = k0; kk < k0 + kchunk; kk += 16) {
        float4 a = *(const float4*)(Ap + kk);
        float4 b = *(const float4*)(Bp + kk);
        __syncthreads();
        As[lcol + 0][lrow] = a.x; As[lcol + 1][lrow] = a.y;
        As[lcol + 2][lrow] = a.z; As[lcol + 3][lrow] = a.w;
        Bs[lcol + 0][lrow] = b.x; Bs[lcol + 1][lrow] = b.y;
        Bs[lcol + 2][lrow] = b.z; Bs[lcol + 3][lrow] = b.w;
        __syncthreads();
#pragma unroll
        for (int k = 0; k < 16; k++) {
            float4 av = *(const float4*)&As[k][ty << 2];
            float4 bv = *(const float4*)&Bs[k][tx << 2];
            float aa[4] = {av.x, av.y, av.z, av.w};
            float bb[4] = {bv.x, bv.y, bv.z, bv.w};
#pragma unroll
            for (int i = 0; i < 4; i++)
#pragma unroll
                for (int j = 0; j < 4; j++)
                    acc[i][j] = fmaf(aa[i], bb[j], acc[i][j]);
        }
    }
    int row = ty << 2, col = n0 + (tx << 2);
#pragma unroll
    for (int i = 0; i < 4; i++)
#pragma unroll
        for (int j = 0; j < 4; j++)
            atomicAdd(&C[(size_t)(row + i) * DD + col + j], acc[i][j]);
}

// ---------------- idx 1: both input GEMMs (z=0: W_in ; z=1: W_out B-half) ----
__global__ __launch_bounds__(256) void gemm_dual(const float* __restrict__ inp,
                                                 const float* __restrict__ Win,
                                                 const float* __restrict__ Wout) {
    if (blockIdx.z == 0)
        gemm_body(inp, DD, Win, DD, g_target, DD / 8,
                  blockIdx.x * 64, blockIdx.y * (DD / 8));
    else
        gemm_body(inp, DD, Wout + DD, 2 * DD, g_acc5, DD / 8,
                  blockIdx.x * 64, blockIdx.y * (DD / 8));
}

// ---------------- idx 3: fused attention, cp.async smem ring ----------------
// grid (SPLIT, BB), 256 threads / 8 warps, 2 CTAs/SM. Warp w, pair p covers
// rows 16p+2w, 16p+2w+1 (4 KB contiguous). Depth-3 ring: 2 pairs in flight
// during compute. Pairwise online softmax (R4-proven math).
__global__ __launch_bounds__(256, 2) void attn_pass(const float* __restrict__ ctx,
                                                    float* __restrict__ attn0,
                                                    float* __restrict__ attn1) {
    extern __shared__ __align__(16) float sm[];
    float* ring = sm;                 // [w][stage][row][512]
    float* sqm  = sm + RING_F;        // [k][j][lane][4]
    float* sacc = sqm + 1024;         // [2][512]
    float* slog = sacc + 1024;        // [2][128]
    float* smx  = slog + 256;         // [2][8]
    float* ssm  = smx + 16;           // [2][8]

    const int b = blockIdx.y, sp = blockIdx.x;
    const int tid = threadIdx.x, lane = tid & 31, w = tid >> 5;

    // sq[k][j][l][t] = target[b, (l+32j)*8 + 2t + k]  (q_k at d=(l+32j)*4+t)
    {
        int k = tid >> 7, j = (tid >> 5) & 3, l = tid & 31;
        const float* g = g_target + (size_t)b * DD + (size_t)(l + 32 * j) * 8 + k;
        float4 v; v.x = g[0]; v.y = g[2]; v.z = g[4]; v.w = g[6];
        *(float4*)&sqm[((k * 4 + j) * 32 + l) * 4] = v;
    }
    for (int i = tid; i < 2 * DH; i += 256) sacc[i] = 0.f;
    __syncthreads();

    const float* cbase = ctx + ((size_t)b * LL + (size_t)sp * LC) * DH;

    // prefetch pair p into stage s: 1024 floats, 8 x 16B per lane
    auto pf = [&](int p, int s) {
        const float* src = cbase + (size_t)(16 * p + 2 * w) * DH + lane * 4;
        float* dst = ring + (size_t)((w * 3 + s) * 2) * 512 + lane * 4;
#pragma unroll
        for (int i = 0; i < 8; i++)
            __pipeline_memcpy_async(dst + i * 128, src + i * 128, 16);
    };

    float a0[16], a1[16];
#pragma unroll
    for (int i = 0; i < 16; i++) { a0[i] = 0.f; a1[i] = 0.f; }
    float m0 = -1e30f, m1 = -1e30f, s0 = 0.f, s1 = 0.f;

    pf(0, 0); __pipeline_commit();
    pf(1, 1); __pipeline_commit();

#pragma unroll
    for (int p = 0; p < NPAIR; p++) {
        const int st = p % 3;
        __pipeline_wait_prior(1);          // pair p resident (uniform commit count)
        __syncwarp();
        if (p + 2 < NPAIR) pf(p + 2, (p + 2) % 3);   // overwrites stage (p-1)%3
        __pipeline_commit();               // ALWAYS commit: keeps wait math exact

        const float* rA = ring + (size_t)((w * 3 + st) * 2) * 512;
        const float* rB = rA + 512;

        float cA[16], cB[16];
#pragma unroll
        for (int j = 0; j < 4; j++) {
            float4 va = *(const float4*)&rA[(lane + 32 * j) * 4];
            float4 vb = *(const float4*)&rB[(lane + 32 * j) * 4];
            cA[4 * j + 0] = va.x; cA[4 * j + 1] = va.y; cA[4 * j + 2] = va.z; cA[4 * j + 3] = va.w;
            cB[4 * j + 0] = vb.x; cB[4 * j + 1] = vb.y; cB[4 * j + 2] = vb.z; cB[4 * j + 3] = vb.w;
        }

        float dA0 = 0.f, dA1 = 0.f, dB0 = 0.f, dB1 = 0.f;
#pragma unroll
        for (int j = 0; j < 4; j++) {
            float4 q0v = *(const float4*)&sqm[((0 * 4 + j) * 32 + lane) * 4];
            float4 q1v = *(const float4*)&sqm[((1 * 4 + j) * 32 + lane) * 4];
            dA0 = fmaf(cA[4*j+0], q0v.x, dA0); dA0 = fmaf(cA[4*j+1], q0v.y, dA0);
            dA0 = fmaf(cA[4*j+2], q0v.z, dA0); dA0 = fmaf(cA[4*j+3], q0v.w, dA0);
            dA1 = fmaf(cA[4*j+0], q1v.x, dA1); dA1 = fmaf(cA[4*j+1], q1v.y, dA1);
            dA1 = fmaf(cA[4*j+2], q1v.z, dA1); dA1 = fmaf(cA[4*j+3], q1v.w, dA1);
            dB0 = fmaf(cB[4*j+0], q0v.x, dB0); dB0 = fmaf(cB[4*j+1], q0v.y, dB0);
            dB0 = fmaf(cB[4*j+2], q0v.z, dB0); dB0 = fmaf(cB[4*j+3], q0v.w, dB0);
            dB1 = fmaf(cB[4*j+0], q1v.x, dB1); dB1 = fmaf(cB[4*j+1], q1v.y, dB1);
            dB1 = fmaf(cB[4*j+2], q1v.z, dB1); dB1 = fmaf(cB[4*j+3], q1v.w, dB1);
        }
#pragma unroll
        for (int o = 16; o; o >>= 1) {
            dA0 += __shfl_xor_sync(0xffffffffu, dA0, o);
            dA1 += __shfl_xor_sync(0xffffffffu, dA1, o);
            dB0 += __shfl_xor_sync(0xffffffffu, dB0, o);
            dB1 += __shfl_xor_sync(0xffffffffu, dB1, o);
        }
        int r = 16 * p + 2 * w;
        if (lane == 0) {
            slog[0 * 128 + r] = dA0; slog[0 * 128 + r + 1] = dB0;
            slog[1 * 128 + r] = dA1; slog[1 * 128 + r + 1] = dB1;
        }
        // pairwise online softmax; r==1 exactly when max unchanged (exp(0)=1)
        float n0 = fmaxf(m0, fmaxf(dA0, dB0));
        float n1 = fmaxf(m1, fmaxf(dA1, dB1));
        float r0 = __expf(m0 - n0), r1 = __expf(m1 - n1);
        float eA0 = __expf(dA0 - n0), eB0 = __expf(dB0 - n0);
        float eA1 = __expf(dA1 - n1), eB1 = __expf(dB1 - n1);
        s0 = s0 * r0 + eA0 + eB0; m0 = n0;
        s1 = s1 * r1 + eA1 + eB1; m1 = n1;
        if (r0 != 1.f || r1 != 1.f) {
#pragma unroll
            for (int i = 0; i < 16; i++) { a0[i] *= r0; a1[i] *= r1; }
        }
#pragma unroll
        for (int i = 0; i < 16; i++) {
            a0[i] = fmaf(eB0, cB[i], fmaf(eA0, cA[i], a0[i]));
            a1[i] = fmaf(eB1, cB[i], fmaf(eA1, cA[i], a1[i]));
        }
    }

    // ---- combine 8 warps within the CTA ----
    if (lane == 0) {
        smx[0 * 8 + w] = m0; smx[1 * 8 + w] = m1;
        ssm[0 * 8 + w] = s0; ssm[1 * 8 + w] = s1;
    }
    __syncthreads();

    // bulk coalesced store of raw logits (normalized later in final_k)
    {
        float* a0p = attn0 + (size_t)b * LL + sp * LC;
        float* a1p = attn1 + (size_t)b * LL + sp * LC;
        for (int i = tid; i < LC; i += 256) {
            a0p[i] = slog[0 * 128 + i];
            a1p[i] = slog[1 * 128 + i];
        }
    }

    float M0 = -1e30f, M1 = -1e30f;
#pragma unroll
    for (int ww = 0; ww < 8; ww++) {
        M0 = fmaxf(M0, smx[0 * 8 + ww]);
        M1 = fmaxf(M1, smx[1 * 8 + ww]);
    }
    float f0 = __expf(m0 - M0);
    float f1 = __expf(m1 - M1);
#pragma unroll
    for (int j = 0; j < 4; j++)
#pragma unroll
        for (int t = 0; t < 4; t++) {
            int d = (lane + 32 * j) * 4 + t;
            atomicAdd(&sacc[d],      a0[4 * j + t] * f0);
            atomicAdd(&sacc[DH + d], a1[4 * j + t] * f1);
        }
    __syncthreads();

    int idx0 = (b * 2 + 0) * SPLIT + sp;
    int idx1 = (b * 2 + 1) * SPLIT + sp;
    if (tid == 0) {
        float S0 = 0.f, S1 = 0.f;
#pragma unroll
        for (int ww = 0; ww < 8; ww++) {
            S0 += ssm[0 * 8 + ww] * __expf(smx[0 * 8 + ww] - M0);
            S1 += ssm[1 * 8 + ww] * __expf(smx[1 * 8 + ww] - M1);
        }
        g_pm[idx0] = M0; g_ps[idx0] = S0;
        g_pm[idx1] = M1; g_ps[idx1] = S1;
    }
    for (int i = tid; i < DH; i += 256) {
        g_pacc[(size_t)idx0 * DH + i] = sacc[i];
        g_pacc[(size_t)idx1 * DH + i] = sacc[DH + i];
    }
}

// ---------------- idx 4: combine SPLIT partials (parallel M/S) ----------------
__global__ __launch_bounds__(256) void combine2() {
    int bk = blockIdx.x;                 // 0..127 = b*2+k
    __shared__ float wgt[SPLIT];
    __shared__ float sInv;
    if (threadIdx.x < 16) {
        float mv = g_pm[bk * SPLIT + threadIdx.x];
        float M = mv;
#pragma unroll
        for (int o = 8; o; o >>= 1) M = fmaxf(M, __shfl_xor_sync(0x0000ffffu, M, o));
        float wv = __expf(mv - M);
        wgt[threadIdx.x] = wv;
        float sv = g_ps[bk * SPLIT + threadIdx.x] * wv;
#pragma unroll
        for (int o = 8; o; o >>= 1) sv += __shfl_xor_sync(0x0000ffffu, sv, o);
        if (threadIdx.x == 0) {
            float inv = 1.0f / sv;
            sInv = inv;
            g_ms[bk * 2] = M; g_ms[bk * 2 + 1] = inv;
        }
    }
    __syncthreads();
    float inv = sInv;
    int b = bk >> 1, k = bk & 1;
    const float* pa = g_pacc + (size_t)bk * SPLIT * DH;
    for (int d = threadIdx.x; d < DH; d += 256) {
        float acc = 0.f;
#pragma unroll
        for (int sp = 0; sp < SPLIT; sp++) acc += pa[(size_t)sp * DH + d] * wgt[sp];
        g_wctx[(size_t)b * DD + k * DH + d] = acc * inv;
    }
}

// ---------------- idx 5: output GEMM + tanh, co-scheduled attn norm ----------
__global__ __launch_bounds__(256) void final_k(const float* __restrict__ Wout,
                                               float* __restrict__ out) {
    if (blockIdx.x < 128) {
        int tile = blockIdx.x >> 3, split = blockIdx.x & 7;
        gemm_body(g_wctx, DD, Wout, 2 * DD, g_acc5, DD / 8,
                  tile * 64, split * (DD / 8));
        __threadfence();
        __shared__ unsigned s_old;
        __syncthreads();
        if (threadIdx.x == 0) s_old = atomicAdd(&g_tile_ctr[tile], 1u);
        __syncthreads();
        if (s_old == 7u) {
            __threadfence();
            int n0 = tile * 64;
            for (int i = threadIdx.x; i < 64 * 64; i += 256) {
                int r = i >> 6, c = i & 63;
                out[(size_t)r * DD + n0 + c] = tanhf(g_acc5[(size_t)r * DD + n0 + c]);
            }
        }
    } else {
        float* attn = out + BB * DD;     // [attn0 | attn1], each BB*LL
        int start = (blockIdx.x - 128) * 256 + threadIdx.x;
        for (int i = start; i < 2 * BB * LL; i += 64 * 256) {
            int k = i >> 17;
            int b = (i & (BB * LL - 1)) >> 11;
            int bk = b * 2 + k;
            attn[i] = __expf(attn[i] - g_ms[bk * 2]) * g_ms[bk * 2 + 1];
        }
    }
}

// ---------------- launcher ----------------
extern "C" void kernel_launch(void* const* d_in, const int* in_sizes, int n_in,
                              void* d_out, int out_size) {
    const float* input   = (const float*)d_in[0]; // [64,1024]
    const float* context = (const float*)d_in[1]; // [64,2048,512]
    const float* W_in    = (const float*)d_in[2]; // [1024,1024]
    const float* W_out   = (const float*)d_in[3]; // [1024,2048]
    float* out = (float*)d_out;                   // [ctxOut | attn0 | attn1]

    static int smem_set = 0;
    if (!smem_set) {
        cudaFuncSetAttribute(attn_pass, cudaFuncAttributeMaxDynamicSharedMemorySize, SMEM_B);
        smem_set = 1;
    }

    prep_kernel<<<256, 256>>>();                             // idx 0
    gemm_dual<<<dim3(16, 8, 2), 256>>>(input, W_in, W_out);  // idx 1
    zero_ctr<<<1, 32>>>();                                   // idx 2
    attn_pass<<<dim3(SPLIT, BB), 256, SMEM_B>>>(             // idx 3 (profiled)
        context, out + BB * DD, out + BB * DD + BB * LL);
    combine2<<<128, 256>>>();                                // idx 4
    final_k<<<192, 256>>>(W_out, out);                       // idx 5
}